// round 4
// baseline (speedup 1.0000x reference)
#include <cuda_runtime.h>
#include <math.h>

#define NN   50000
#define EE   800000
#define KDIM 128
#define HH   8
#define CC   16
#define EDIMC 16
#define OUTC 64

typedef unsigned long long ull;

// ------------------------- device scratch (no allocs allowed) ----------------
__device__ float g_xl[NN * KDIM];
__device__ float g_xr[NN * KDIM];
__device__ float g_h [NN * KDIM];
__device__ int   g_deg[NN];
__device__ int   g_off[NN];
__device__ int   g_cur[NN];
__device__ int   g_eid[EE];
__device__ int   g_bsum[64];
__device__ int   g_boff[64];

// ------------------------- f32x2 helpers (packed fp32) -----------------------
__device__ __forceinline__ ull pack2(float a, float b) {
    ull r;
    asm("mov.b64 %0, {%1, %2};" : "=l"(r) : "f"(a), "f"(b));
    return r;
}
__device__ __forceinline__ ull fma2(ull a, ull b, ull c) {
    ull d;
    asm("fma.rn.f32x2 %0, %1, %2, %3;" : "=l"(d) : "l"(a), "l"(b), "l"(c));
    return d;
}
__device__ __forceinline__ ull add2(ull a, ull b) {
    ull d;
    asm("add.rn.f32x2 %0, %1, %2;" : "=l"(d) : "l"(a), "l"(b));
    return d;
}
__device__ __forceinline__ void unpack2(ull v, float& a, float& b) {
    asm("mov.b64 {%0, %1}, %2;" : "=f"(a), "=f"(b) : "l"(v));
}
__device__ __forceinline__ void prefetchL1(const void* p) {
    asm volatile("prefetch.global.L1 [%0];" :: "l"(p));
}

// ------------------------- CSR build -----------------------------------------
__global__ void k_zero_deg() {
    int i = blockIdx.x * 256 + threadIdx.x;
    if (i < NN) g_deg[i] = 0;
}

__global__ void k_hist(const int* __restrict__ dst) {
    int e = blockIdx.x * 256 + threadIdx.x;
    if (e < EE) atomicAdd(&g_deg[dst[e]], 1);
}

__global__ __launch_bounds__(1024) void k_scan1() {
    __shared__ int wsum[32];
    int t = threadIdx.x;
    int i = blockIdx.x * 1024 + t;
    int v = (i < NN) ? g_deg[i] : 0;
    int x = v;
#pragma unroll
    for (int o = 1; o < 32; o <<= 1) {
        int y = __shfl_up_sync(0xffffffffu, x, o);
        if ((t & 31) >= o) x += y;
    }
    if ((t & 31) == 31) wsum[t >> 5] = x;
    __syncthreads();
    if (t < 32) {
        int s = wsum[t];
#pragma unroll
        for (int o = 1; o < 32; o <<= 1) {
            int y = __shfl_up_sync(0xffffffffu, s, o);
            if (t >= o) s += y;
        }
        wsum[t] = s;
    }
    __syncthreads();
    int base = (t >= 32) ? wsum[(t >> 5) - 1] : 0;
    int incl = x + base;
    if (i < NN) g_off[i] = incl - v;
    if (t == 1023) g_bsum[blockIdx.x] = incl;
}

__global__ void k_scan2(int nb) {
    __shared__ int s[64];
    int t = threadIdx.x;
    int v = (t < nb) ? g_bsum[t] : 0;
    s[t] = v;
    __syncthreads();
#pragma unroll
    for (int o = 1; o < 64; o <<= 1) {
        int x = (t >= o) ? s[t - o] : 0;
        __syncthreads();
        s[t] += x;
        __syncthreads();
    }
    if (t < nb) g_boff[t] = s[t] - v;
}

__global__ void k_fixup() {
    int i = blockIdx.x * 256 + threadIdx.x;
    if (i < NN) {
        int o = g_off[i] + g_boff[i / 1024];
        g_off[i] = o;
        g_cur[i] = o;
    }
}

__global__ void k_scatter(const int* __restrict__ dst) {
    int e = blockIdx.x * 256 + threadIdx.x;
    if (e < EE) {
        int d = dst[e];
        int p = atomicAdd(&g_cur[d], 1);
        g_eid[p] = e;
    }
}

// deterministic edge order: warp-per-node rank sort (deg<=32), serial fallback
__global__ void k_sort() {
    int gw = (blockIdx.x * 256 + threadIdx.x) >> 5;
    int lane = threadIdx.x & 31;
    if (gw >= NN) return;
    int st = g_off[gw], n = g_deg[gw];
    if (n <= 1) return;
    if (n <= 32) {
        int e = (lane < n) ? g_eid[st + lane] : 0x7fffffff;
        int rank = 0;
#pragma unroll
        for (int j = 0; j < 32; j++) {
            int ej = __shfl_sync(0xffffffffu, e, j);
            rank += (ej < e);
        }
        __syncwarp();
        if (lane < n) g_eid[st + rank] = e;
    } else if (lane == 0) {
        for (int i = 1; i < n; i++) {
            int key = g_eid[st + i];
            int j = i - 1;
            while (j >= 0 && g_eid[st + j] > key) {
                g_eid[st + j + 1] = g_eid[st + j];
                j--;
            }
            g_eid[st + j + 1] = key;
        }
    }
}

// ------------------------- register-blocked GEMM (k-chunked, dual-W) ---------
// Y[n,NCOLS] = X[n,128] @ W[128,NCOLS] + b.  gridDim.y selects (W0,b0,Y0) or
// (W1,b1,Y1).  K is processed in 2 chunks of 64 so smem = 32K(W)+32K(X)
// -> 2 blocks/SM (16 warps) instead of 1.
template <int NCOLS>
__global__ __launch_bounds__(256, 2) void gemm_kernel(
    const float* __restrict__ X,
    const float* __restrict__ W0, const float* __restrict__ b0, float* __restrict__ Y0,
    const float* __restrict__ W1, const float* __restrict__ b1, float* __restrict__ Y1,
    int nrows)
{
    constexpr int NCT = NCOLS / 16;       // cols per thread: 8 or 4
    constexpr int NP  = NCT / 2;          // f32x2 pairs: 4 or 2
    const float* W    = blockIdx.y ? W1 : W0;
    const float* bias = blockIdx.y ? b1 : b0;
    float*       Y    = blockIdx.y ? Y1 : Y0;

    extern __shared__ float sm[];
    float* ws = sm;                        // [64 * NCOLS] (k-chunk, c)
    float* xs = sm + 64 * NCOLS;           // [64 * 128]   k-major (k, r)
    int tid  = threadIdx.x;
    int row0 = blockIdx.x * 128;

    int tc = tid & 15, tr = tid >> 4;
    int c0 = tc * NCT;
    int r0 = tr * 8;

    ull acc[8][NP];
#pragma unroll
    for (int i = 0; i < 8; i++)
#pragma unroll
        for (int p = 0; p < NP; p++) acc[i][p] = 0ull;

#pragma unroll
    for (int kc = 0; kc < 2; kc++) {
        if (kc) __syncthreads();
        {   // load W chunk
            const float4* w4 = (const float4*)W;
            float4* s4 = (float4*)ws;
            constexpr int WT = 64 * NCOLS / 4;
#pragma unroll
            for (int i = tid; i < WT; i += 256) s4[i] = w4[kc * WT + i];
        }
        {   // load X chunk transposed: xs[k*128 + r] = X[row0+r][kc*64+k]
#pragma unroll
            for (int i = tid; i < 128 * 16; i += 256) {
                int r  = i & 127;
                int k4 = i >> 7;           // 0..15
                int gr = row0 + r;
                float4 val = (gr < nrows)
                    ? *(const float4*)(X + (size_t)gr * 128 + kc * 64 + k4 * 4)
                    : make_float4(0.f, 0.f, 0.f, 0.f);
                xs[(k4 * 4 + 0) * 128 + r] = val.x;
                xs[(k4 * 4 + 1) * 128 + r] = val.y;
                xs[(k4 * 4 + 2) * 128 + r] = val.z;
                xs[(k4 * 4 + 3) * 128 + r] = val.w;
            }
        }
        __syncthreads();

#pragma unroll 4
        for (int k = 0; k < 64; k++) {
            float4 xa = *(const float4*)&xs[k * 128 + r0];
            float4 xb = *(const float4*)&xs[k * 128 + r0 + 4];
            ull wv[NP];
            {
                const ulonglong2* wp = (const ulonglong2*)&ws[k * NCOLS + c0];
                ulonglong2 t0 = wp[0];
                wv[0] = t0.x; wv[1] = t0.y;
                if (NP == 4) {
                    ulonglong2 t1 = wp[1];
                    wv[2] = t1.x; wv[3] = t1.y;
                }
            }
            float xv[8] = {xa.x, xa.y, xa.z, xa.w, xb.x, xb.y, xb.z, xb.w};
#pragma unroll
            for (int i = 0; i < 8; i++) {
                ull x2 = pack2(xv[i], xv[i]);
#pragma unroll
                for (int p = 0; p < NP; p++)
                    acc[i][p] = fma2(x2, wv[p], acc[i][p]);
            }
        }
    }

    float bl[NCT];
#pragma unroll
    for (int j = 0; j < NCT; j++) bl[j] = bias[c0 + j];

#pragma unroll
    for (int i = 0; i < 8; i++) {
        int gr = row0 + r0 + i;
        if (gr < nrows) {
            float o[NCT];
#pragma unroll
            for (int p = 0; p < NP; p++) unpack2(acc[i][p], o[2 * p], o[2 * p + 1]);
#pragma unroll
            for (int j = 0; j < NCT; j++) o[j] += bl[j];
            float4* yp = (float4*)(Y + (size_t)gr * NCOLS + c0);
#pragma unroll
            for (int q = 0; q < NCT / 4; q++)
                yp[q] = make_float4(o[4 * q], o[4 * q + 1], o[4 * q + 2], o[4 * q + 3]);
        }
    }
}

// ------------------------- fused GATv2 aggregation ---------------------------
// 2 warps per node (even/odd edges), lane owns 4 channels. Latency hidden by
// prefetch.global.L1 (2 edges ahead) instead of register double-buffering ->
// ~112 live regs, no spills, 4 blocks/SM.
__global__ __launch_bounds__(128, 4) void k_agg(
    const float* __restrict__ xl, const float* __restrict__ xr,
    const int*   __restrict__ src_arr, const float* __restrict__ ea,
    const float* __restrict__ We, const float* __restrict__ att,
    const float* __restrict__ bias, float* __restrict__ out)
{
    __shared__ float sWe[EDIMC * KDIM];
    __shared__ float sAtt[KDIM];
    __shared__ float sPart[2][5][32];
    int tid = threadIdx.x;
    {
        const float4* w4 = (const float4*)We;
        float4* s4 = (float4*)sWe;
#pragma unroll
        for (int i = tid; i < 512; i += 128) s4[i] = w4[i];
    }
    sAtt[tid] = att[tid];
    __syncthreads();

    int warp = tid >> 5, lane = tid & 31;
    int slot = warp >> 1;
    int sub  = warp & 1;
    int v = blockIdx.x * 2 + slot;       // NN even -> always valid
    int c0 = lane * 4;

    ull w0[EDIMC], w1[EDIMC];
#pragma unroll
    for (int k = 0; k < EDIMC; k++) {
        ulonglong2 t2 = *(const ulonglong2*)&sWe[k * KDIM + c0];
        w0[k] = t2.x; w1[k] = t2.y;
    }
    float4 av  = *(const float4*)&sAtt[c0];
    float4 xr4 = *(const float4*)(xr + (size_t)v * KDIM + c0);
    int st = g_off[v], dg = g_deg[v];

    float a0 = 0.f, a1 = 0.f, a2 = 0.f, a3 = 0.f, den = 0.f;

    int i = sub;
    int eA = 0, sA = 0, eB = 0, sB = 0, eC = 0;
    if (i < dg)     { eA = g_eid[st + i];     sA = src_arr[eA]; }
    if (i + 2 < dg) { eB = g_eid[st + i + 2]; sB = src_arr[eB]; }
    if (i + 4 < dg) { eC = g_eid[st + i + 4]; }

    for (; i < dg; i += 2) {
        bool hasC = (i + 4 < dg), hasD = (i + 6 < dg);
        int sC = 0, eD = 0;
        if (hasC) {
            sC = src_arr[eC];
            // prefetch data 2 edges ahead (ready when eC becomes current)
            prefetchL1(ea + (size_t)eC * EDIMC);
            prefetchL1(xl + (size_t)sC * KDIM + c0);
        }
        if (hasD) eD = g_eid[st + i + 6];

        const float4* p = (const float4*)(ea + (size_t)eA * EDIMC);
        float4 ea0 = p[0], ea1 = p[1], ea2 = p[2], ea3 = p[3];
        float4 xl4 = *(const float4*)(xl + (size_t)sA * KDIM + c0);

        ull q0 = 0ull, q1 = 0ull, r0 = 0ull, r1 = 0ull;
#define EE_STEP(vala, valb, k)                                        \
        { ull ta = pack2(vala, vala); ull tb = pack2(valb, valb);     \
          q0 = fma2(ta, w0[k], q0);     q1 = fma2(ta, w1[k], q1);     \
          r0 = fma2(tb, w0[k + 1], r0); r1 = fma2(tb, w1[k + 1], r1); }
        EE_STEP(ea0.x, ea0.y, 0)
        EE_STEP(ea0.z, ea0.w, 2)
        EE_STEP(ea1.x, ea1.y, 4)
        EE_STEP(ea1.z, ea1.w, 6)
        EE_STEP(ea2.x, ea2.y, 8)
        EE_STEP(ea2.z, ea2.w, 10)
        EE_STEP(ea3.x, ea3.y, 12)
        EE_STEP(ea3.z, ea3.w, 14)
#undef EE_STEP
        ull p0 = add2(q0, r0), p1 = add2(q1, r1);
        float ee0, ee1, ee2, ee3;
        unpack2(p0, ee0, ee1);
        unpack2(p1, ee2, ee3);

        float m0 = xl4.x + xr4.x + ee0; m0 = fmaxf(m0, 0.2f * m0);
        float m1 = xl4.y + xr4.y + ee1; m1 = fmaxf(m1, 0.2f * m1);
        float m2 = xl4.z + xr4.z + ee2; m2 = fmaxf(m2, 0.2f * m2);
        float m3 = xl4.w + xr4.w + ee3; m3 = fmaxf(m3, 0.2f * m3);

        float lg = m0 * av.x;
        lg = fmaf(m1, av.y, lg);
        lg = fmaf(m2, av.z, lg);
        lg = fmaf(m3, av.w, lg);
        lg += __shfl_xor_sync(0xffffffffu, lg, 1);
        lg += __shfl_xor_sync(0xffffffffu, lg, 2);

        float ex = __expf(lg);
        a0 = fmaf(ex, xl4.x, a0);
        a1 = fmaf(ex, xl4.y, a1);
        a2 = fmaf(ex, xl4.z, a2);
        a3 = fmaf(ex, xl4.w, a3);
        den += ex;

        eA = eB; sA = sB;
        eB = eC; sB = sC;
        eC = eD;
    }

    if (sub == 1) {
        sPart[slot][0][lane] = a0;
        sPart[slot][1][lane] = a1;
        sPart[slot][2][lane] = a2;
        sPart[slot][3][lane] = a3;
        sPart[slot][4][lane] = den;
    }
    __syncthreads();
    if (sub == 0) {
        a0  += sPart[slot][0][lane];
        a1  += sPart[slot][1][lane];
        a2  += sPart[slot][2][lane];
        a3  += sPart[slot][3][lane];
        den += sPart[slot][4][lane];
        float inv = 1.0f / (den + 1e-16f);
        float4 b4 = *(const float4*)(bias + c0);
        float o0 = a0 * inv + b4.x;
        float o1 = a1 * inv + b4.y;
        float o2 = a2 * inv + b4.z;
        float o3 = a3 * inv + b4.w;
        o0 = (o0 > 0.f) ? o0 : expm1f(o0);
        o1 = (o1 > 0.f) ? o1 : expm1f(o1);
        o2 = (o2 > 0.f) ? o2 : expm1f(o2);
        o3 = (o3 > 0.f) ? o3 : expm1f(o3);
        *(float4*)(out + (size_t)v * KDIM + c0) = make_float4(o0, o1, o2, o3);
    }
}

// ------------------------- launch --------------------------------------------
extern "C" void kernel_launch(void* const* d_in, const int* in_sizes, int n_in,
                              void* d_out, int out_size)
{
    const float* x    = (const float*)d_in[0];
    const int*   ei   = (const int*)  d_in[1];
    const float* ea   = (const float*)d_in[2];
    const float* Wl1  = (const float*)d_in[3];
    const float* bl1  = (const float*)d_in[4];
    const float* Wr1  = (const float*)d_in[5];
    const float* br1  = (const float*)d_in[6];
    const float* We1  = (const float*)d_in[7];
    const float* att1 = (const float*)d_in[8];
    const float* b1   = (const float*)d_in[9];
    const float* Wl2  = (const float*)d_in[10];
    const float* bl2  = (const float*)d_in[11];
    const float* Wr2  = (const float*)d_in[12];
    const float* br2  = (const float*)d_in[13];
    const float* We2  = (const float*)d_in[14];
    const float* att2 = (const float*)d_in[15];
    const float* b2   = (const float*)d_in[16];
    const float* Wc   = (const float*)d_in[17];
    const float* bc   = (const float*)d_in[18];

    float *xl, *xr, *hbuf;
    cudaGetSymbolAddress((void**)&xl,   g_xl);
    cudaGetSymbolAddress((void**)&xr,   g_xr);
    cudaGetSymbolAddress((void**)&hbuf, g_h);

    const int* srcp = ei;
    const int* dstp = ei + EE;

    const int SMEM128 = (64 * 128 + 64 * 128) * 4;   // 65536 B
    const int SMEM64  = (64 * 64  + 64 * 128) * 4;   // 49152 B
    cudaFuncSetAttribute((const void*)gemm_kernel<128>,
                         cudaFuncAttributeMaxDynamicSharedMemorySize, SMEM128);
    cudaFuncSetAttribute((const void*)gemm_kernel<64>,
                         cudaFuncAttributeMaxDynamicSharedMemorySize, SMEM64);

    dim3 ggrid2((NN + 127) / 128, 2);
    dim3 ggrid1((NN + 127) / 128, 1);
    dim3 agrid(NN / 2);
    int sortg = (NN * 32 + 255) / 256;

    // ---- CSR build interleaved with layer-1 GEMMs ----
    k_zero_deg<<<(NN + 255) / 256, 256>>>();
    k_hist<<<(EE + 255) / 256, 256>>>(dstp);
    k_scan1<<<(NN + 1023) / 1024, 1024>>>();
    gemm_kernel<128><<<ggrid2, 256, SMEM128>>>(x, Wl1, bl1, xl, Wr1, br1, xr, NN);
    k_scan2<<<1, 64>>>((NN + 1023) / 1024);
    k_fixup<<<(NN + 255) / 256, 256>>>();
    k_scatter<<<(EE + 255) / 256, 256>>>(dstp);
    k_sort<<<sortg, 256>>>();

    // ---- layer 1 aggregation ----
    k_agg<<<agrid, 128>>>(xl, xr, srcp, ea, We1, att1, b1, hbuf);

    // ---- layer 2 ----
    gemm_kernel<128><<<ggrid2, 256, SMEM128>>>(hbuf, Wl2, bl2, xl, Wr2, br2, xr, NN);
    k_agg<<<agrid, 128>>>(xl, xr, srcp, ea, We2, att2, b2, hbuf);

    // ---- classifier ----
    gemm_kernel<64><<<ggrid1, 256, SMEM64>>>(hbuf, Wc, bc, (float*)d_out,
                                             Wc, bc, (float*)d_out, NN);
}

// round 6
// speedup vs baseline: 1.1203x; 1.1203x over previous
#include <cuda_runtime.h>
#include <math.h>

#define NN   50000
#define EE   800000
#define KDIM 128
#define HH   8
#define CC   16
#define EDIMC 16
#define OUTC 64

typedef unsigned long long ull;

// ------------------------- device scratch (no allocs allowed) ----------------
__device__ float g_xl[NN * KDIM];
__device__ float g_xr[NN * KDIM];
__device__ float g_h [NN * KDIM];
__device__ float g_ea[(size_t)EE * EDIMC];   // edge_attr permuted to CSR order
__device__ int   g_src[EE];                  // src node permuted to CSR order
__device__ int   g_deg[NN];
__device__ int   g_off[NN];
__device__ int   g_cur[NN];
__device__ int   g_eid[EE];
__device__ int   g_bsum[64];
__device__ int   g_boff[64];

// ------------------------- f32x2 helpers (packed fp32) -----------------------
__device__ __forceinline__ ull pack2(float a, float b) {
    ull r;
    asm("mov.b64 %0, {%1, %2};" : "=l"(r) : "f"(a), "f"(b));
    return r;
}
__device__ __forceinline__ ull fma2(ull a, ull b, ull c) {
    ull d;
    asm("fma.rn.f32x2 %0, %1, %2, %3;" : "=l"(d) : "l"(a), "l"(b), "l"(c));
    return d;
}
__device__ __forceinline__ ull add2(ull a, ull b) {
    ull d;
    asm("add.rn.f32x2 %0, %1, %2;" : "=l"(d) : "l"(a), "l"(b));
    return d;
}
__device__ __forceinline__ void unpack2(ull v, float& a, float& b) {
    asm("mov.b64 {%0, %1}, %2;" : "=f"(a), "=f"(b) : "l"(v));
}
__device__ __forceinline__ void prefetchL1(const void* p) {
    asm volatile("prefetch.global.L1 [%0];" :: "l"(p));
}

// ------------------------- CSR build -----------------------------------------
__global__ void k_zero_deg() {
    int i = blockIdx.x * 256 + threadIdx.x;
    if (i < NN) g_deg[i] = 0;
}

__global__ void k_hist(const int* __restrict__ dst) {
    int e = blockIdx.x * 256 + threadIdx.x;
    if (e < EE) atomicAdd(&g_deg[dst[e]], 1);
}

__global__ __launch_bounds__(1024) void k_scan1() {
    __shared__ int wsum[32];
    int t = threadIdx.x;
    int i = blockIdx.x * 1024 + t;
    int v = (i < NN) ? g_deg[i] : 0;
    int x = v;
#pragma unroll
    for (int o = 1; o < 32; o <<= 1) {
        int y = __shfl_up_sync(0xffffffffu, x, o);
        if ((t & 31) >= o) x += y;
    }
    if ((t & 31) == 31) wsum[t >> 5] = x;
    __syncthreads();
    if (t < 32) {
        int s = wsum[t];
#pragma unroll
        for (int o = 1; o < 32; o <<= 1) {
            int y = __shfl_up_sync(0xffffffffu, s, o);
            if (t >= o) s += y;
        }
        wsum[t] = s;
    }
    __syncthreads();
    int base = (t >= 32) ? wsum[(t >> 5) - 1] : 0;
    int incl = x + base;
    if (i < NN) g_off[i] = incl - v;
    if (t == 1023) g_bsum[blockIdx.x] = incl;
}

__global__ void k_scan2(int nb) {
    __shared__ int s[64];
    int t = threadIdx.x;
    int v = (t < nb) ? g_bsum[t] : 0;
    s[t] = v;
    __syncthreads();
#pragma unroll
    for (int o = 1; o < 64; o <<= 1) {
        int x = (t >= o) ? s[t - o] : 0;
        __syncthreads();
        s[t] += x;
        __syncthreads();
    }
    if (t < nb) g_boff[t] = s[t] - v;
}

__global__ void k_fixup() {
    int i = blockIdx.x * 256 + threadIdx.x;
    if (i < NN) {
        int o = g_off[i] + g_boff[i / 1024];
        g_off[i] = o;
        g_cur[i] = o;
    }
}

__global__ void k_scatter(const int* __restrict__ dst) {
    int e = blockIdx.x * 256 + threadIdx.x;
    if (e < EE) {
        int d = dst[e];
        int p = atomicAdd(&g_cur[d], 1);
        g_eid[p] = e;
    }
}

// deterministic edge order: warp-per-node rank sort (deg<=32), serial fallback
__global__ void k_sort() {
    int gw = (blockIdx.x * 256 + threadIdx.x) >> 5;
    int lane = threadIdx.x & 31;
    if (gw >= NN) return;
    int st = g_off[gw], n = g_deg[gw];
    if (n <= 1) return;
    if (n <= 32) {
        int e = (lane < n) ? g_eid[st + lane] : 0x7fffffff;
        int rank = 0;
#pragma unroll
        for (int j = 0; j < 32; j++) {
            int ej = __shfl_sync(0xffffffffu, e, j);
            rank += (ej < e);
        }
        __syncwarp();
        if (lane < n) g_eid[st + rank] = e;
    } else if (lane == 0) {
        for (int i = 1; i < n; i++) {
            int key = g_eid[st + i];
            int j = i - 1;
            while (j >= 0 && g_eid[st + j] > key) {
                g_eid[st + j + 1] = g_eid[st + j];
                j--;
            }
            g_eid[st + j + 1] = key;
        }
    }
}

// permute edge_attr + src into CSR slot order (coalesced writes)
__global__ void k_permute(const int* __restrict__ src, const float* __restrict__ ea) {
    int t = blockIdx.x * 256 + threadIdx.x;
    int p = t >> 2, j = t & 3;
    if (p < EE) {
        int e = g_eid[p];
        if (j == 0) g_src[p] = src[e];
        float4 v = ((const float4*)(ea + (size_t)e * EDIMC))[j];
        ((float4*)(g_ea + (size_t)p * EDIMC))[j] = v;
    }
}

// ------------------------- register-blocked GEMM (k-chunked, dual-W) ---------
template <int NCOLS>
__global__ __launch_bounds__(256, 2) void gemm_kernel(
    const float* __restrict__ X,
    const float* __restrict__ W0, const float* __restrict__ b0, float* __restrict__ Y0,
    const float* __restrict__ W1, const float* __restrict__ b1, float* __restrict__ Y1,
    int nrows)
{
    constexpr int NCT = NCOLS / 16;
    constexpr int NP  = NCT / 2;
    const float* W    = blockIdx.y ? W1 : W0;
    const float* bias = blockIdx.y ? b1 : b0;
    float*       Y    = blockIdx.y ? Y1 : Y0;

    extern __shared__ float sm[];
    float* ws = sm;                        // [64 * NCOLS]
    float* xs = sm + 64 * NCOLS;           // [64 * 128] k-major
    int tid  = threadIdx.x;
    int row0 = blockIdx.x * 128;

    int tc = tid & 15, tr = tid >> 4;
    int c0 = tc * NCT;
    int r0 = tr * 8;

    ull acc[8][NP];
#pragma unroll
    for (int i = 0; i < 8; i++)
#pragma unroll
        for (int p = 0; p < NP; p++) acc[i][p] = 0ull;

#pragma unroll
    for (int kc = 0; kc < 2; kc++) {
        if (kc) __syncthreads();
        {
            const float4* w4 = (const float4*)W;
            float4* s4 = (float4*)ws;
            constexpr int WT = 64 * NCOLS / 4;
#pragma unroll
            for (int i = tid; i < WT; i += 256) s4[i] = w4[kc * WT + i];
        }
        {
#pragma unroll
            for (int i = tid; i < 128 * 16; i += 256) {
                int r  = i & 127;
                int k4 = i >> 7;
                int gr = row0 + r;
                float4 val = (gr < nrows)
                    ? *(const float4*)(X + (size_t)gr * 128 + kc * 64 + k4 * 4)
                    : make_float4(0.f, 0.f, 0.f, 0.f);
                xs[(k4 * 4 + 0) * 128 + r] = val.x;
                xs[(k4 * 4 + 1) * 128 + r] = val.y;
                xs[(k4 * 4 + 2) * 128 + r] = val.z;
                xs[(k4 * 4 + 3) * 128 + r] = val.w;
            }
        }
        __syncthreads();

#pragma unroll 4
        for (int k = 0; k < 64; k++) {
            float4 xa = *(const float4*)&xs[k * 128 + r0];
            float4 xb = *(const float4*)&xs[k * 128 + r0 + 4];
            ull wv[NP];
            {
                const ulonglong2* wp = (const ulonglong2*)&ws[k * NCOLS + c0];
                ulonglong2 t0 = wp[0];
                wv[0] = t0.x; wv[1] = t0.y;
                if (NP == 4) {
                    ulonglong2 t1 = wp[1];
                    wv[2] = t1.x; wv[3] = t1.y;
                }
            }
            float xv[8] = {xa.x, xa.y, xa.z, xa.w, xb.x, xb.y, xb.z, xb.w};
#pragma unroll
            for (int i = 0; i < 8; i++) {
                ull x2 = pack2(xv[i], xv[i]);
#pragma unroll
                for (int p = 0; p < NP; p++)
                    acc[i][p] = fma2(x2, wv[p], acc[i][p]);
            }
        }
    }

    float bl[NCT];
#pragma unroll
    for (int j = 0; j < NCT; j++) bl[j] = bias[c0 + j];

#pragma unroll
    for (int i = 0; i < 8; i++) {
        int gr = row0 + r0 + i;
        if (gr < nrows) {
            float o[NCT];
#pragma unroll
            for (int p = 0; p < NP; p++) unpack2(acc[i][p], o[2 * p], o[2 * p + 1]);
#pragma unroll
            for (int j = 0; j < NCT; j++) o[j] += bl[j];
            float4* yp = (float4*)(Y + (size_t)gr * NCOLS + c0);
#pragma unroll
            for (int q = 0; q < NCT / 4; q++)
                yp[q] = make_float4(o[4 * q], o[4 * q + 1], o[4 * q + 2], o[4 * q + 3]);
        }
    }
}

// ------------------------- fused GATv2 aggregation ---------------------------
// 2 warps per node, each takes a contiguous half of the node's CSR edge range.
// ea/src are CSR-permuted -> contiguous; whole range bulk-prefetched at warp
// start, src nodes register-resident (shfl-indexed) so xl rows prefetch early.
__global__ __launch_bounds__(128, 4) void k_agg(
    const float* __restrict__ xl, const float* __restrict__ xr,
    const float* __restrict__ We, const float* __restrict__ att,
    const float* __restrict__ bias, float* __restrict__ out)
{
    __shared__ float sWe[EDIMC * KDIM];
    __shared__ float sAtt[KDIM];
    __shared__ float sPart[2][5][32];
    int tid = threadIdx.x;
    {
        const float4* w4 = (const float4*)We;
        float4* s4 = (float4*)sWe;
#pragma unroll
        for (int i = tid; i < 512; i += 128) s4[i] = w4[i];
    }
    sAtt[tid] = att[tid];
    __syncthreads();

    int warp = tid >> 5, lane = tid & 31;
    int slot = warp >> 1;
    int sub  = warp & 1;
    int v = blockIdx.x * 2 + slot;       // NN even -> always valid
    int c0 = lane * 4;

    ull w0[EDIMC], w1[EDIMC];
#pragma unroll
    for (int k = 0; k < EDIMC; k++) {
        ulonglong2 t2 = *(const ulonglong2*)&sWe[k * KDIM + c0];
        w0[k] = t2.x; w1[k] = t2.y;
    }
    float4 av  = *(const float4*)&sAtt[c0];
    float4 xr4 = *(const float4*)(xr + (size_t)v * KDIM + c0);
    int st = g_off[v], dg = g_deg[v];

    int half = (dg + 1) >> 1;
    int b    = st + (sub ? half : 0);
    int cnt  = sub ? (dg - half) : half;

    // ---- bulk prefetch: ea range (contiguous) ----
    if (2 * lane < cnt) prefetchL1(g_ea + (size_t)(b + 2 * lane) * EDIMC);

    // ---- register-resident src list + xl row prefetch ----
    int srcs = (lane < cnt) ? g_src[b + lane] : 0;
    for (int jb = 0; jb < cnt; jb += 8) {
        int r  = jb + (lane >> 2);
        int rs = __shfl_sync(0xffffffffu, srcs, r & 31);
        if (r < cnt)
            prefetchL1((const char*)(xl + (size_t)rs * KDIM) + (lane & 3) * 128);
    }

    float a0 = 0.f, a1 = 0.f, a2 = 0.f, a3 = 0.f, den = 0.f;

    for (int i = 0; i < cnt; i++) {
        int s = (i < 32) ? __shfl_sync(0xffffffffu, srcs, i) : g_src[b + i];
        const float4* p = (const float4*)(g_ea + (size_t)(b + i) * EDIMC);
        float4 ea0 = p[0], ea1 = p[1], ea2 = p[2], ea3 = p[3];
        float4 xl4 = *(const float4*)(xl + (size_t)s * KDIM + c0);

        ull q0 = 0ull, q1 = 0ull, r0 = 0ull, r1 = 0ull;
#define EE_STEP(vala, valb, k)                                        \
        { ull ta = pack2(vala, vala); ull tb = pack2(valb, valb);     \
          q0 = fma2(ta, w0[k], q0);     q1 = fma2(ta, w1[k], q1);     \
          r0 = fma2(tb, w0[k + 1], r0); r1 = fma2(tb, w1[k + 1], r1); }
        EE_STEP(ea0.x, ea0.y, 0)
        EE_STEP(ea0.z, ea0.w, 2)
        EE_STEP(ea1.x, ea1.y, 4)
        EE_STEP(ea1.z, ea1.w, 6)
        EE_STEP(ea2.x, ea2.y, 8)
        EE_STEP(ea2.z, ea2.w, 10)
        EE_STEP(ea3.x, ea3.y, 12)
        EE_STEP(ea3.z, ea3.w, 14)
#undef EE_STEP
        ull p0 = add2(q0, r0), p1 = add2(q1, r1);
        float ee0, ee1, ee2, ee3;
        unpack2(p0, ee0, ee1);
        unpack2(p1, ee2, ee3);

        float m0 = xl4.x + xr4.x + ee0; m0 = fmaxf(m0, 0.2f * m0);
        float m1 = xl4.y + xr4.y + ee1; m1 = fmaxf(m1, 0.2f * m1);
        float m2 = xl4.z + xr4.z + ee2; m2 = fmaxf(m2, 0.2f * m2);
        float m3 = xl4.w + xr4.w + ee3; m3 = fmaxf(m3, 0.2f * m3);

        float lg = m0 * av.x;
        lg = fmaf(m1, av.y, lg);
        lg = fmaf(m2, av.z, lg);
        lg = fmaf(m3, av.w, lg);
        lg += __shfl_xor_sync(0xffffffffu, lg, 1);
        lg += __shfl_xor_sync(0xffffffffu, lg, 2);

        float ex = __expf(lg);
        a0 = fmaf(ex, xl4.x, a0);
        a1 = fmaf(ex, xl4.y, a1);
        a2 = fmaf(ex, xl4.z, a2);
        a3 = fmaf(ex, xl4.w, a3);
        den += ex;
    }

    if (sub == 1) {
        sPart[slot][0][lane] = a0;
        sPart[slot][1][lane] = a1;
        sPart[slot][2][lane] = a2;
        sPart[slot][3][lane] = a3;
        sPart[slot][4][lane] = den;
    }
    __syncthreads();
    if (sub == 0) {
        a0  += sPart[slot][0][lane];
        a1  += sPart[slot][1][lane];
        a2  += sPart[slot][2][lane];
        a3  += sPart[slot][3][lane];
        den += sPart[slot][4][lane];
        float inv = 1.0f / (den + 1e-16f);
        float4 b4 = *(const float4*)(bias + c0);
        float o0 = a0 * inv + b4.x;
        float o1 = a1 * inv + b4.y;
        float o2 = a2 * inv + b4.z;
        float o3 = a3 * inv + b4.w;
        o0 = (o0 > 0.f) ? o0 : expm1f(o0);
        o1 = (o1 > 0.f) ? o1 : expm1f(o1);
        o2 = (o2 > 0.f) ? o2 : expm1f(o2);
        o3 = (o3 > 0.f) ? o3 : expm1f(o3);
        *(float4*)(out + (size_t)v * KDIM + c0) = make_float4(o0, o1, o2, o3);
    }
}

// ------------------------- launch --------------------------------------------
extern "C" void kernel_launch(void* const* d_in, const int* in_sizes, int n_in,
                              void* d_out, int out_size)
{
    const float* x    = (const float*)d_in[0];
    const int*   ei   = (const int*)  d_in[1];
    const float* ea   = (const float*)d_in[2];
    const float* Wl1  = (const float*)d_in[3];
    const float* bl1  = (const float*)d_in[4];
    const float* Wr1  = (const float*)d_in[5];
    const float* br1  = (const float*)d_in[6];
    const float* We1  = (const float*)d_in[7];
    const float* att1 = (const float*)d_in[8];
    const float* b1   = (const float*)d_in[9];
    const float* Wl2  = (const float*)d_in[10];
    const float* bl2  = (const float*)d_in[11];
    const float* Wr2  = (const float*)d_in[12];
    const float* br2  = (const float*)d_in[13];
    const float* We2  = (const float*)d_in[14];
    const float* att2 = (const float*)d_in[15];
    const float* b2   = (const float*)d_in[16];
    const float* Wc   = (const float*)d_in[17];
    const float* bc   = (const float*)d_in[18];

    float *xl, *xr, *hbuf;
    cudaGetSymbolAddress((void**)&xl,   g_xl);
    cudaGetSymbolAddress((void**)&xr,   g_xr);
    cudaGetSymbolAddress((void**)&hbuf, g_h);

    const int* srcp = ei;
    const int* dstp = ei + EE;

    const int SMEM128 = (64 * 128 + 64 * 128) * 4;   // 65536 B
    const int SMEM64  = (64 * 64  + 64 * 128) * 4;   // 49152 B
    cudaFuncSetAttribute((const void*)gemm_kernel<128>,
                         cudaFuncAttributeMaxDynamicSharedMemorySize, SMEM128);
    cudaFuncSetAttribute((const void*)gemm_kernel<64>,
                         cudaFuncAttributeMaxDynamicSharedMemorySize, SMEM64);

    dim3 ggrid2((NN + 127) / 128, 2);
    dim3 ggrid1((NN + 127) / 128, 1);
    dim3 agrid(NN / 2);
    int sortg = (NN * 32 + 255) / 256;

    // ---- CSR build interleaved with layer-1 GEMMs ----
    k_zero_deg<<<(NN + 255) / 256, 256>>>();
    k_hist<<<(EE + 255) / 256, 256>>>(dstp);
    k_scan1<<<(NN + 1023) / 1024, 1024>>>();
    gemm_kernel<128><<<ggrid2, 256, SMEM128>>>(x, Wl1, bl1, xl, Wr1, br1, xr, NN);
    k_scan2<<<1, 64>>>((NN + 1023) / 1024);
    k_fixup<<<(NN + 255) / 256, 256>>>();
    k_scatter<<<(EE + 255) / 256, 256>>>(dstp);
    k_sort<<<sortg, 256>>>();
    k_permute<<<(EE * 4 + 255) / 256, 256>>>(srcp, ea);

    // ---- layer 1 aggregation ----
    k_agg<<<agrid, 128>>>(xl, xr, We1, att1, b1, hbuf);

    // ---- layer 2 ----
    gemm_kernel<128><<<ggrid2, 256, SMEM128>>>(hbuf, Wl2, bl2, xl, Wr2, br2, xr, NN);
    k_agg<<<agrid, 128>>>(xl, xr, We2, att2, b2, hbuf);

    // ---- classifier ----
    gemm_kernel<64><<<ggrid1, 256, SMEM64>>>(hbuf, Wc, bc, (float*)d_out,
                                             Wc, bc, (float*)d_out, NN);
}